// round 12
// baseline (speedup 1.0000x reference)
#include <cuda_runtime.h>

#define NB 8
#define CC 64
#define LL 512
#define DD 64
#define ITILE 32
#define NTHREADS 512

#define TWO_LOG2E 2.8853900817779268f  // 2*log2(e)

// Scratch (allocation-free rule: __device__ globals)
__device__ float g_q2[NB * LL * DD];    // [n][l][d]   2log2e * (xt@Wt)
__device__ float g_kbT2[NB * DD * LL];  // [n][d][l]   2log2e * (xt@Wx + bh), transposed

__device__ __forceinline__ float ex2_fast(float x) {
    float y;
    asm("ex2.approx.f32 %0, %1;" : "=f"(y) : "f"(x));
    return y;
}
__device__ __forceinline__ float rcp_fast(float x) {
    float y;
    asm("rcp.approx.f32 %0, %1;" : "=f"(y) : "f"(x));
    return y;
}

// ---------------------------------------------------------------------------
// Projection kernel: q2 = 2log2e*(xt@Wt), kbT2 = 2log2e*((xt@Wx + bh)^T)
// grid (NB, LL/64), 256 threads
// ---------------------------------------------------------------------------
__global__ void proj_kernel(const float* __restrict__ x,
                            const float* __restrict__ Wx,
                            const float* __restrict__ Wt,
                            const float* __restrict__ bh) {
    __shared__ float xs[CC * 64];   // x[n][c][l0+l]
    __shared__ float wts[CC * DD];
    __shared__ float wxs[CC * DD];
    const int n = blockIdx.x;
    const int l0 = blockIdx.y * 64;
    const int t = threadIdx.x;

    for (int idx = t; idx < CC * 64; idx += 256) {
        int c = idx >> 6, l = idx & 63;
        xs[idx] = x[((size_t)n * CC + c) * LL + l0 + l];
    }
    for (int idx = t; idx < CC * DD; idx += 256) {
        wts[idx] = Wt[idx];
        wxs[idx] = Wx[idx];
    }
    __syncthreads();

    const int l = t & 63;       // lanes -> consecutive l (conflict-free xs reads)
    const int dgrp = t >> 6;    // warp-uniform (broadcast W reads)
    #pragma unroll 1
    for (int dd = 0; dd < 16; dd++) {
        const int d = dgrp * 16 + dd;
        float aq = 0.f, ak = 0.f;
        #pragma unroll 8
        for (int c = 0; c < CC; c++) {
            float xv = xs[c * 64 + l];
            aq = fmaf(xv, wts[c * DD + d], aq);
            ak = fmaf(xv, wxs[c * DD + d], ak);
        }
        g_q2[((size_t)n * LL + l0 + l) * DD + d] = aq * TWO_LOG2E;
        g_kbT2[((size_t)n * DD + d) * LL + l0 + l] = (ak + bh[d]) * TWO_LOG2E;
    }
}

// ---------------------------------------------------------------------------
// Fused scores + softmax + banded AV kernel.
// grid: NB * (LL/ITILE) = 128 blocks, 512 threads, ~205 KB dynamic smem.
// Warp w owns rows i_loc = {w, w+16}. Lanes sweep j.
//
// Score identity: Wa.tanh(q+k+bh) = sum_d Wa_d - 2*sum_d Wa_d*rcp(ex2(arg2)+1),
// arg2 = 2log2e*(q+k+bh) (pre-scaled operands). Inner loop: 1 FADD + EX2 +
// 1 FADD + RCP + 1 FFMA per element.
// ---------------------------------------------------------------------------
__global__ void __launch_bounds__(NTHREADS, 1)
attn_kernel(const float* __restrict__ x,
            const float* __restrict__ Wa,
            const float* __restrict__ ba,
            float* __restrict__ v_out,
            float* __restrict__ a_out) {
    extern __shared__ float sm[];
    float* kbT = sm;                                // [DD][LL]   32768 floats
    float* sc  = sm + DD * LL;                      // [ITILE][LL] 16384 floats
    float* qs  = sm + DD * LL + ITILE * LL;         // [ITILE][DD]  2048 floats
    float* was = qs + ITILE * DD;                   // [DD] holds -2*Wa
    float* wsp = was + DD;                          // [1]  holds sum(Wa)
    float* xw  = sm;                                // reused in phase 3: [CC][97]

    const int nb = blockIdx.x >> 4;           // / (LL/ITILE)
    const int i0 = (blockIdx.x & 15) * ITILE;
    const int t = threadIdx.x;
    const int lane = t & 31;
    const int w = t >> 5;

    // Stage kbT slab (128KB), q tile, Wa
    const float* gk = g_kbT2 + (size_t)nb * DD * LL;
    for (int idx = t; idx < DD * LL; idx += NTHREADS) kbT[idx] = gk[idx];
    const float* gq = g_q2 + ((size_t)nb * LL + i0) * DD;
    for (int idx = t; idx < ITILE * DD; idx += NTHREADS) qs[idx] = gq[idx];
    if (t < DD) was[t] = -2.0f * Wa[t];
    if (t == 0) {
        float s = 0.f;
        #pragma unroll
        for (int d = 0; d < DD; d++) s += Wa[d];
        wsp[0] = s;
    }
    __syncthreads();

    const float base = wsp[0] + ba[0];   // sum(Wa) + ba

    // ---- Phase 1: scores for ALL j (full-row max is semantically required) ----
    #pragma unroll 1
    for (int half = 0; half < 2; half++) {
        const int il = w + half * 16;
        const float* qrow = qs + il * DD;
        float acc[16];
        #pragma unroll
        for (int k = 0; k < 16; k++) acc[k] = 0.f;

        #pragma unroll 4
        for (int d = 0; d < DD; d++) {
            const float qv = qrow[d];       // smem broadcast (pre-scaled)
            const float wv = was[d];        // smem broadcast (-2*Wa_d)
            const float* kr = kbT + d * LL + (lane << 2);
            #pragma unroll
            for (int ch = 0; ch < 4; ch++) {
                float4 kv = *(const float4*)(kr + ch * 128);  // conflict-free
                float r0 = rcp_fast(ex2_fast(qv + kv.x) + 1.0f);
                float r1 = rcp_fast(ex2_fast(qv + kv.y) + 1.0f);
                float r2 = rcp_fast(ex2_fast(qv + kv.z) + 1.0f);
                float r3 = rcp_fast(ex2_fast(qv + kv.w) + 1.0f);
                acc[ch * 4 + 0] = fmaf(wv, r0, acc[ch * 4 + 0]);
                acc[ch * 4 + 1] = fmaf(wv, r1, acc[ch * 4 + 1]);
                acc[ch * 4 + 2] = fmaf(wv, r2, acc[ch * 4 + 2]);
                acc[ch * 4 + 3] = fmaf(wv, r3, acc[ch * 4 + 3]);
            }
        }
        float* row = sc + il * LL;
        #pragma unroll
        for (int ch = 0; ch < 4; ch++) {
            float4 v4 = make_float4(acc[ch * 4 + 0] + base, acc[ch * 4 + 1] + base,
                                    acc[ch * 4 + 2] + base, acc[ch * 4 + 3] + base);
            *(float4*)(row + ch * 128 + (lane << 2)) = v4;
        }
    }
    // No barrier: each warp consumes only its own score rows.

    // ---- Phase 2: full-row max -> banded exp -> normalize -> write a ----
    #pragma unroll 1
    for (int half = 0; half < 2; half++) {
        const int il = w + half * 16;
        const int ig = i0 + il;
        float* row = sc + il * LL;
        float sv[16];
        float mx = -3.4e38f;
        #pragma unroll
        for (int k = 0; k < 16; k++) {
            sv[k] = row[lane + (k << 5)];
            mx = fmaxf(mx, sv[k]);
        }
        #pragma unroll
        for (int o = 16; o > 0; o >>= 1)
            mx = fmaxf(mx, __shfl_xor_sync(0xffffffffu, mx, o));

        float ssum = 0.f;
        #pragma unroll
        for (int k = 0; k < 16; k++) {
            const int j = lane + (k << 5);
            const int dj = j - ig;
            float e = (dj >= -32 && dj <= 31) ? __expf(sv[k] - mx) : 0.f;
            sv[k] = e;
            ssum += e;
        }
        #pragma unroll
        for (int o = 16; o > 0; o >>= 1)
            ssum += __shfl_xor_sync(0xffffffffu, ssum, o);
        const float inv = 1.0f / (ssum + 1e-6f);

        float* arow = a_out + ((size_t)(nb * LL + ig)) * LL;
        #pragma unroll
        for (int k = 0; k < 16; k++) {
            const int j = lane + (k << 5);
            const float av = sv[k] * inv;
            row[j] = av;          // keep normalized a in smem for phase 3
            arow[j] = av;         // coalesced global write (full row incl. zeros)
        }
    }
    __syncthreads();  // all warps done reading kbT before xw overwrites it

    // ---- Phase 3: v[n,c,i] = sum_{j in band} a[i,j] * x[n,c,j] ----
    const int jlo = max(0, i0 - 32);
    const int jhi = min(LL, i0 + ITILE - 1 + 32);  // exclusive; width <= 95
    const int wwidth = jhi - jlo;
    for (int idx = t; idx < CC * 96; idx += NTHREADS) {
        const int c = idx / 96, jw = idx % 96;
        if (jw < wwidth)
            xw[c * 97 + jw] = x[((size_t)nb * CC + c) * LL + jlo + jw];
    }
    __syncthreads();

    #pragma unroll 1
    for (int half = 0; half < 2; half++) {
        const int il = w + half * 16;
        const int ig = i0 + il;
        const int js = max(0, ig - 32);
        const int je = min(LL, ig + 32);
        const float* arow = sc + il * LL;
        const float* xr0 = xw + lane * 97 - jlo;           // stride-97: conflict-free
        const float* xr1 = xw + (lane + 32) * 97 - jlo;
        float a0 = 0.f, a1 = 0.f;
        for (int j = js; j < je; j++) {
            const float av = arow[j];                      // smem broadcast
            a0 = fmaf(av, xr0[j], a0);
            a1 = fmaf(av, xr1[j], a1);
        }
        v_out[((size_t)nb * CC + lane) * LL + ig] = a0;
        v_out[((size_t)nb * CC + lane + 32) * LL + ig] = a1;
    }
}

// ---------------------------------------------------------------------------
extern "C" void kernel_launch(void* const* d_in, const int* in_sizes, int n_in,
                              void* d_out, int out_size) {
    const float* x  = (const float*)d_in[0];
    const float* Wx = (const float*)d_in[1];
    const float* Wt = (const float*)d_in[2];
    const float* bh = (const float*)d_in[3];
    const float* Wa = (const float*)d_in[4];
    const float* ba = (const float*)d_in[5];

    float* out = (float*)d_out;
    float* v_out = out;                      // (N, C, L) = 262144 floats
    float* a_out = out + NB * CC * LL;       // (N, L, L) = 2097152 floats

    proj_kernel<<<dim3(NB, LL / 64), 256>>>(x, Wx, Wt, bh);

    const int smem_bytes = (DD * LL + ITILE * LL + ITILE * DD + DD + 1) * 4;  // 205060
    cudaFuncSetAttribute(attn_kernel,
                         cudaFuncAttributeMaxDynamicSharedMemorySize, smem_bytes);
    attn_kernel<<<NB * (LL / ITILE), NTHREADS, smem_bytes>>>(x, Wa, ba, v_out, a_out);
}

// round 13
// speedup vs baseline: 1.3640x; 1.3640x over previous
#include <cuda_runtime.h>

#define NB 8
#define CC 64
#define LL 512
#define DD 64
#define ITILE 32
#define NTHREADS 512

// Scratch (allocation-free rule: __device__ globals)
__device__ float g_q[NB * LL * DD];    // [n][l][d]   xt@Wt
__device__ float g_kbT[NB * DD * LL];  // [n][d][l]   (xt@Wx + bh)^T

// Single-MUFU tanh (sm_75+). Elementwise err ~3e-4 abs; aggregated over the
// D=64 Wa dot -> ~1e-4 score err, well under the 1e-3 rel_err gate (measured
// baseline with exact tanh: 2.4e-7).
__device__ __forceinline__ float tanh_fast(float x) {
    float y;
    asm("tanh.approx.f32 %0, %1;" : "=f"(y) : "f"(x));
    return y;
}

// ---------------------------------------------------------------------------
// Projection kernel: q = xt@Wt, kbT = (xt@Wx + bh)^T
// grid (NB, LL/64), 256 threads
// ---------------------------------------------------------------------------
__global__ void proj_kernel(const float* __restrict__ x,
                            const float* __restrict__ Wx,
                            const float* __restrict__ Wt,
                            const float* __restrict__ bh) {
    __shared__ float xs[CC * 64];   // x[n][c][l0+l]
    __shared__ float wts[CC * DD];
    __shared__ float wxs[CC * DD];
    const int n = blockIdx.x;
    const int l0 = blockIdx.y * 64;
    const int t = threadIdx.x;

    for (int idx = t; idx < CC * 64; idx += 256) {
        int c = idx >> 6, l = idx & 63;
        xs[idx] = x[((size_t)n * CC + c) * LL + l0 + l];
    }
    for (int idx = t; idx < CC * DD; idx += 256) {
        wts[idx] = Wt[idx];
        wxs[idx] = Wx[idx];
    }
    __syncthreads();

    const int l = t & 63;       // lanes -> consecutive l (conflict-free xs reads)
    const int dgrp = t >> 6;    // warp-uniform (broadcast W reads)
    #pragma unroll 1
    for (int dd = 0; dd < 16; dd++) {
        const int d = dgrp * 16 + dd;
        float aq = 0.f, ak = 0.f;
        #pragma unroll 8
        for (int c = 0; c < CC; c++) {
            float xv = xs[c * 64 + l];
            aq = fmaf(xv, wts[c * DD + d], aq);
            ak = fmaf(xv, wxs[c * DD + d], ak);
        }
        g_q[((size_t)n * LL + l0 + l) * DD + d] = aq;
        g_kbT[((size_t)n * DD + d) * LL + l0 + l] = ak + bh[d];
    }
}

// ---------------------------------------------------------------------------
// Fused scores + softmax + banded AV kernel.
// grid: NB * (LL/ITILE) = 128 blocks, 512 threads, ~205 KB dynamic smem.
// Warp w owns rows i_loc = {w, w+16}. Lanes sweep j.
// Inner element: FADD + MUFU.TANH + FFMA (1 MUFU, was 2 with EX2+RCP).
// ---------------------------------------------------------------------------
__global__ void __launch_bounds__(NTHREADS, 1)
attn_kernel(const float* __restrict__ x,
            const float* __restrict__ Wa,
            const float* __restrict__ ba,
            float* __restrict__ v_out,
            float* __restrict__ a_out) {
    extern __shared__ float sm[];
    float* kbT = sm;                                // [DD][LL]   32768 floats
    float* sc  = sm + DD * LL;                      // [ITILE][LL] 16384 floats
    float* qs  = sm + DD * LL + ITILE * LL;         // [ITILE][DD]  2048 floats
    float* was = qs + ITILE * DD;                   // [DD] Wa
    float* xw  = sm;                                // reused in phase 3: [CC][97]

    const int nb = blockIdx.x >> 4;           // / (LL/ITILE)
    const int i0 = (blockIdx.x & 15) * ITILE;
    const int t = threadIdx.x;
    const int lane = t & 31;
    const int w = t >> 5;

    // Stage kbT slab (128KB), q tile, Wa
    const float* gk = g_kbT + (size_t)nb * DD * LL;
    for (int idx = t; idx < DD * LL; idx += NTHREADS) kbT[idx] = gk[idx];
    const float* gq = g_q + ((size_t)nb * LL + i0) * DD;
    for (int idx = t; idx < ITILE * DD; idx += NTHREADS) qs[idx] = gq[idx];
    if (t < DD) was[t] = Wa[t];
    __syncthreads();

    const float bav = ba[0];

    // ---- Phase 1: scores for ALL j (full-row max is semantically required) ----
    #pragma unroll 1
    for (int half = 0; half < 2; half++) {
        const int il = w + half * 16;
        const float* qrow = qs + il * DD;
        float acc[16];
        #pragma unroll
        for (int k = 0; k < 16; k++) acc[k] = 0.f;

        #pragma unroll 4
        for (int d = 0; d < DD; d++) {
            const float qv = qrow[d];       // smem broadcast
            const float wv = was[d];        // smem broadcast
            const float* kr = kbT + d * LL + (lane << 2);
            #pragma unroll
            for (int ch = 0; ch < 4; ch++) {
                float4 kv = *(const float4*)(kr + ch * 128);  // conflict-free
                acc[ch * 4 + 0] = fmaf(wv, tanh_fast(qv + kv.x), acc[ch * 4 + 0]);
                acc[ch * 4 + 1] = fmaf(wv, tanh_fast(qv + kv.y), acc[ch * 4 + 1]);
                acc[ch * 4 + 2] = fmaf(wv, tanh_fast(qv + kv.z), acc[ch * 4 + 2]);
                acc[ch * 4 + 3] = fmaf(wv, tanh_fast(qv + kv.w), acc[ch * 4 + 3]);
            }
        }
        float* row = sc + il * LL;
        #pragma unroll
        for (int ch = 0; ch < 4; ch++) {
            float4 v4 = make_float4(acc[ch * 4 + 0] + bav, acc[ch * 4 + 1] + bav,
                                    acc[ch * 4 + 2] + bav, acc[ch * 4 + 3] + bav);
            *(float4*)(row + ch * 128 + (lane << 2)) = v4;
        }
    }
    // No barrier: each warp consumes only its own score rows.

    // ---- Phase 2: full-row max -> banded exp -> normalize -> write a ----
    #pragma unroll 1
    for (int half = 0; half < 2; half++) {
        const int il = w + half * 16;
        const int ig = i0 + il;
        float* row = sc + il * LL;
        float sv[16];
        float mx = -3.4e38f;
        #pragma unroll
        for (int k = 0; k < 16; k++) {
            sv[k] = row[lane + (k << 5)];
            mx = fmaxf(mx, sv[k]);
        }
        #pragma unroll
        for (int o = 16; o > 0; o >>= 1)
            mx = fmaxf(mx, __shfl_xor_sync(0xffffffffu, mx, o));

        float ssum = 0.f;
        #pragma unroll
        for (int k = 0; k < 16; k++) {
            const int j = lane + (k << 5);
            const int dj = j - ig;
            float e = (dj >= -32 && dj <= 31) ? __expf(sv[k] - mx) : 0.f;
            sv[k] = e;
            ssum += e;
        }
        #pragma unroll
        for (int o = 16; o > 0; o >>= 1)
            ssum += __shfl_xor_sync(0xffffffffu, ssum, o);
        const float inv = 1.0f / (ssum + 1e-6f);

        float* arow = a_out + ((size_t)(nb * LL + ig)) * LL;
        #pragma unroll
        for (int k = 0; k < 16; k++) {
            const int j = lane + (k << 5);
            const float av = sv[k] * inv;
            row[j] = av;          // keep normalized a in smem for phase 3
            arow[j] = av;         // coalesced global write (full row incl. zeros)
        }
    }
    __syncthreads();  // all warps done reading kbT before xw overwrites it

    // ---- Phase 3: v[n,c,i] = sum_{j in band} a[i,j] * x[n,c,j] ----
    const int jlo = max(0, i0 - 32);
    const int jhi = min(LL, i0 + ITILE - 1 + 32);  // exclusive; width <= 95
    const int wwidth = jhi - jlo;
    for (int idx = t; idx < CC * 96; idx += NTHREADS) {
        const int c = idx / 96, jw = idx % 96;
        if (jw < wwidth)
            xw[c * 97 + jw] = x[((size_t)nb * CC + c) * LL + jlo + jw];
    }
    __syncthreads();

    #pragma unroll 1
    for (int half = 0; half < 2; half++) {
        const int il = w + half * 16;
        const int ig = i0 + il;
        const int js = max(0, ig - 32);
        const int je = min(LL, ig + 32);
        const float* arow = sc + il * LL;
        const float* xr0 = xw + lane * 97 - jlo;           // stride-97: conflict-free
        const float* xr1 = xw + (lane + 32) * 97 - jlo;
        float a0 = 0.f, a1 = 0.f;
        for (int j = js; j < je; j++) {
            const float av = arow[j];                      // smem broadcast
            a0 = fmaf(av, xr0[j], a0);
            a1 = fmaf(av, xr1[j], a1);
        }
        v_out[((size_t)nb * CC + lane) * LL + ig] = a0;
        v_out[((size_t)nb * CC + lane + 32) * LL + ig] = a1;
    }
}

// ---------------------------------------------------------------------------
extern "C" void kernel_launch(void* const* d_in, const int* in_sizes, int n_in,
                              void* d_out, int out_size) {
    const float* x  = (const float*)d_in[0];
    const float* Wx = (const float*)d_in[1];
    const float* Wt = (const float*)d_in[2];
    const float* bh = (const float*)d_in[3];
    const float* Wa = (const float*)d_in[4];
    const float* ba = (const float*)d_in[5];

    float* out = (float*)d_out;
    float* v_out = out;                      // (N, C, L) = 262144 floats
    float* a_out = out + NB * CC * LL;       // (N, L, L) = 2097152 floats

    proj_kernel<<<dim3(NB, LL / 64), 256>>>(x, Wx, Wt, bh);

    const int smem_bytes = (DD * LL + ITILE * LL + ITILE * DD + DD) * 4;  // 205056
    cudaFuncSetAttribute(attn_kernel,
                         cudaFuncAttributeMaxDynamicSharedMemorySize, smem_bytes);
    attn_kernel<<<NB * (LL / ITILE), NTHREADS, smem_bytes>>>(x, Wa, ba, v_out, a_out);
}

// round 15
// speedup vs baseline: 3.5170x; 2.5785x over previous
#include <cuda_runtime.h>

#define NB 8
#define CC 64
#define LL 512
#define DD 64
#define ITILE 32
#define NTHREADS 512
#define WWIN 96   // padded j-window width (real max 95)

// Scratch (allocation-free rule: __device__ globals)
__device__ float g_q[NB * LL * DD];    // [n][l][d]   xt@Wt
__device__ float g_kbT[NB * DD * LL];  // [n][d][l]   (xt@Wx + bh)^T

__device__ __forceinline__ float tanh_fast(float x) {
    float y;
    asm("tanh.approx.f32 %0, %1;" : "=f"(y) : "f"(x));
    return y;
}

// ---------------------------------------------------------------------------
// Projection: q = xt@Wt, kbT = (xt@Wx + bh)^T
// grid (NB, LL/64, DD/32) = 128 blocks, 256 threads.
// Outer-product register blocking: thread owns 2 l x 4 d x 2 mats.
// Per c: 1 LDS.64 (x) + 2 broadcast LDS.128 (W halves) for 16 FMA.
// ---------------------------------------------------------------------------
__global__ void proj_kernel(const float* __restrict__ x,
                            const float* __restrict__ Wx,
                            const float* __restrict__ Wt,
                            const float* __restrict__ bh) {
    __shared__ float xs[CC * 64];   // x[n][c][l0+l]
    __shared__ float wts[CC * 32];  // Wt[c][dh+dd]
    __shared__ float wxs[CC * 32];  // Wx[c][dh+dd]
    __shared__ float bhs[32];
    const int n  = blockIdx.x;
    const int l0 = blockIdx.y * 64;
    const int dh = blockIdx.z * 32;
    const int t  = threadIdx.x;

    for (int idx = t; idx < CC * 64; idx += 256) {
        int c = idx >> 6, l = idx & 63;
        xs[idx] = x[((size_t)n * CC + c) * LL + l0 + l];
    }
    for (int idx = t; idx < CC * 32; idx += 256) {
        int c = idx >> 5, dd = idx & 31;
        wts[idx] = Wt[c * DD + dh + dd];
        wxs[idx] = Wx[c * DD + dh + dd];
    }
    if (t < 32) bhs[t] = bh[dh + t];
    __syncthreads();

    const int l2 = t & 31;   // lanes -> consecutive float2 of l (conflict-free)
    const int d4 = t >> 5;   // warp-uniform -> broadcast W reads

    float aq[2][4] = {{0.f,0.f,0.f,0.f},{0.f,0.f,0.f,0.f}};
    float ak[2][4] = {{0.f,0.f,0.f,0.f},{0.f,0.f,0.f,0.f}};

    #pragma unroll 8
    for (int c = 0; c < CC; c++) {
        float2 xv = *(const float2*)(xs + c * 64 + 2 * l2);
        float4 wt4 = *(const float4*)(wts + c * 32 + 4 * d4);
        float4 wx4 = *(const float4*)(wxs + c * 32 + 4 * d4);
        float wtk[4] = {wt4.x, wt4.y, wt4.z, wt4.w};
        float wxk[4] = {wx4.x, wx4.y, wx4.z, wx4.w};
        float xvk[2] = {xv.x, xv.y};
        #pragma unroll
        for (int i = 0; i < 2; i++)
            #pragma unroll
            for (int k = 0; k < 4; k++) {
                aq[i][k] = fmaf(xvk[i], wtk[k], aq[i][k]);
                ak[i][k] = fmaf(xvk[i], wxk[k], ak[i][k]);
            }
    }

    #pragma unroll
    for (int i = 0; i < 2; i++) {
        const int l = l0 + 2 * l2 + i;
        *(float4*)(g_q + ((size_t)n * LL + l) * DD + dh + 4 * d4) =
            make_float4(aq[i][0], aq[i][1], aq[i][2], aq[i][3]);
        #pragma unroll
        for (int k = 0; k < 4; k++) {
            const int dd = 4 * d4 + k;
            g_kbT[((size_t)n * DD + dh + dd) * LL + l] = ak[i][k] + bhs[dd];
        }
    }
}

// ---------------------------------------------------------------------------
// Banded scores + register softmax + banded AV.
// grid: NB * (LL/ITILE) = 128 blocks, 512 threads, ~41.5 KB smem.
// Softmax shift = band max (differs from full-row max only through the
// +1e-6 epsilon term; perturbation <= 1e-6/S with S >= 1 -> negligible).
// tanh count: 8x less than full-row version.
// ---------------------------------------------------------------------------
__global__ void __launch_bounds__(NTHREADS, 1)
attn_kernel(const float* __restrict__ x,
            const float* __restrict__ Wa,
            const float* __restrict__ ba,
            float* __restrict__ v_out,
            float* __restrict__ a_out) {
    extern __shared__ float sm[];
    float* kb  = sm;                  // [DD][WWIN] 6144 floats; reused as xw [CC][97] 6208
    float* qs  = sm + 6208;           // [ITILE][DD] 2048
    float* was = qs + ITILE * DD;     // [DD]
    float* ab  = was + DD;            // [ITILE][64] band a, 2048
    float* xw  = sm;                  // phase-3 alias of kb region

    const int nb = blockIdx.x >> 4;
    const int i0 = (blockIdx.x & 15) * ITILE;
    const int t = threadIdx.x;
    const int lane = t & 31;
    const int w = t >> 5;

    const int jlo = max(0, i0 - 32);
    const int jhi = min(LL, i0 + ITILE - 1 + 32);  // exclusive
    const int wwidth = jhi - jlo;                  // <= 95

    // Stage kb window (zero-padded), q tile, Wa
    for (int idx = t; idx < DD * WWIN; idx += NTHREADS) {
        int d = idx / WWIN, jw = idx - d * WWIN;
        kb[idx] = (jw < wwidth) ? g_kbT[((size_t)nb * DD + d) * LL + jlo + jw] : 0.f;
    }
    const float* gq = g_q + ((size_t)nb * LL + i0) * DD;
    for (int idx = t; idx < ITILE * DD; idx += NTHREADS) qs[idx] = gq[idx];
    if (t < DD) was[t] = Wa[t];
    __syncthreads();

    const float bav = ba[0];

    // ---- Phase 1+2: banded scores -> register softmax -> a rows ----
    #pragma unroll 1
    for (int half = 0; half < 2; half++) {
        const int il = w + half * 16;
        const int ig = i0 + il;
        const int js = max(0, ig - 32);
        const int je = min(LL, ig + 32);
        const int count = je - js;      // 33..64
        const int ws = js - jlo;
        const float* qrow = qs + il * DD;

        float s0 = 0.f, s1 = 0.f;       // lane covers band pos {lane, lane+32}
        #pragma unroll 8
        for (int d = 0; d < DD; d++) {
            const float qv = qrow[d];   // smem broadcast
            const float wv = was[d];    // smem broadcast
            const float k0 = kb[d * WWIN + ws + lane];        // conflict-free
            const float k1 = kb[d * WWIN + ws + lane + 32];   // conflict-free
            s0 = fmaf(wv, tanh_fast(qv + k0), s0);
            s1 = fmaf(wv, tanh_fast(qv + k1), s1);
        }
        const bool v1 = (lane + 32) < count;  // pos lane always valid (count>32)
        s0 += bav; s1 += bav;

        float mx = fmaxf(s0, v1 ? s1 : -3.4e38f);
        #pragma unroll
        for (int o = 16; o > 0; o >>= 1)
            mx = fmaxf(mx, __shfl_xor_sync(0xffffffffu, mx, o));

        const float e0 = __expf(s0 - mx);
        const float e1 = v1 ? __expf(s1 - mx) : 0.f;
        float ss = e0 + e1;
        #pragma unroll
        for (int o = 16; o > 0; o >>= 1)
            ss += __shfl_xor_sync(0xffffffffu, ss, o);
        const float inv = 1.0f / (ss + 1e-6f);

        ab[il * 64 + lane]      = e0 * inv;
        ab[il * 64 + lane + 32] = e1 * inv;   // 0 when invalid
        __syncwarp();

        // full a row (zeros outside band), coalesced
        float* arow = a_out + ((size_t)(nb * LL + ig)) * LL;
        #pragma unroll
        for (int k = 0; k < 16; k++) {
            const int j = lane + (k << 5);
            const int p = j - js;
            arow[j] = (p >= 0 && p < 64) ? ab[il * 64 + p] : 0.f;
        }
    }
    __syncthreads();  // all warps done with kb before xw overwrites it

    // ---- Phase 3: v[n,c,i] = sum_{j in band} a[i,j] * x[n,c,j] ----
    for (int idx = t; idx < CC * 96; idx += NTHREADS) {
        const int c = idx / 96, jw = idx % 96;
        if (jw < wwidth)
            xw[c * 97 + jw] = x[((size_t)nb * CC + c) * LL + jlo + jw];
    }
    __syncthreads();

    #pragma unroll 1
    for (int half = 0; half < 2; half++) {
        const int il = w + half * 16;
        const int ig = i0 + il;
        const int js = max(0, ig - 32);
        const int je = min(LL, ig + 32);
        const float* abr = ab + il * 64 - js;              // abr[j], j in [js,je)
        const float* xr0 = xw + lane * 97 - jlo;           // stride-97: conflict-free
        const float* xr1 = xw + (lane + 32) * 97 - jlo;
        float a0 = 0.f, a1 = 0.f;
        for (int j = js; j < je; j++) {
            const float av = abr[j];                       // smem broadcast
            a0 = fmaf(av, xr0[j], a0);
            a1 = fmaf(av, xr1[j], a1);
        }
        v_out[((size_t)nb * CC + lane) * LL + ig] = a0;
        v_out[((size_t)nb * CC + lane + 32) * LL + ig] = a1;
    }
}

// ---------------------------------------------------------------------------
extern "C" void kernel_launch(void* const* d_in, const int* in_sizes, int n_in,
                              void* d_out, int out_size) {
    const float* x  = (const float*)d_in[0];
    const float* Wx = (const float*)d_in[1];
    const float* Wt = (const float*)d_in[2];
    const float* bh = (const float*)d_in[3];
    const float* Wa = (const float*)d_in[4];
    const float* ba = (const float*)d_in[5];

    float* out = (float*)d_out;
    float* v_out = out;                      // (N, C, L) = 262144 floats
    float* a_out = out + NB * CC * LL;       // (N, L, L) = 2097152 floats

    proj_kernel<<<dim3(NB, LL / 64, DD / 32), 256>>>(x, Wx, Wt, bh);

    const int smem_bytes = (6208 + ITILE * DD + DD + ITILE * 64) * 4;  // 41472
    cudaFuncSetAttribute(attn_kernel,
                         cudaFuncAttributeMaxDynamicSharedMemorySize, smem_bytes);
    attn_kernel<<<NB * (LL / ITILE), NTHREADS, smem_bytes>>>(x, Wa, ba, v_out, a_out);
}